// round 14
// baseline (speedup 1.0000x reference)
#include <cuda_runtime.h>
#include <cuda_fp16.h>
#include <cstdint>
#include <cstddef>

#define BATCH 8
#define SEQ   2048
#define HID   256
#define INDIM 96

// ---------------- scratch ----------------
__device__ __align__(256) __half g_q[BATCH * SEQ * HID];
__device__ __align__(256) __half g_k[BATCH * SEQ * HID];
__device__ __align__(256) __half g_v[BATCH * SEQ * HID];

// ---------------- helpers ----------------
__device__ __forceinline__ unsigned f2tf32(float x) {
    unsigned r;
    asm("cvt.rna.tf32.f32 %0, %1;" : "=r"(r) : "f"(x));
    return r;
}
__device__ __forceinline__ void split_tf32(float x, float& hi, float& lo) {
    hi = __uint_as_float(f2tf32(x));
    lo = __uint_as_float(f2tf32(x - hi));
}
__device__ __forceinline__ void mma_tf32(float c[4], const unsigned a[4], const unsigned b[2]) {
    asm("mma.sync.aligned.m16n8k8.row.col.f32.tf32.tf32.f32 "
        "{%0,%1,%2,%3}, {%4,%5,%6,%7}, {%8,%9}, {%0,%1,%2,%3};\n"
        : "+f"(c[0]), "+f"(c[1]), "+f"(c[2]), "+f"(c[3])
        : "r"(a[0]), "r"(a[1]), "r"(a[2]), "r"(a[3]), "r"(b[0]), "r"(b[1]));
}
__device__ __forceinline__ void mma_f16(float c[4], const unsigned a[4], unsigned b0, unsigned b1) {
    asm("mma.sync.aligned.m16n8k16.row.col.f32.f16.f16.f32 "
        "{%0,%1,%2,%3}, {%4,%5,%6,%7}, {%8,%9}, {%0,%1,%2,%3};\n"
        : "+f"(c[0]), "+f"(c[1]), "+f"(c[2]), "+f"(c[3])
        : "r"(a[0]), "r"(a[1]), "r"(a[2]), "r"(a[3]), "r"(b0), "r"(b1));
}
__device__ __forceinline__ void cpa16(void* dst_smem, const void* src) {
    unsigned d = (unsigned)__cvta_generic_to_shared(dst_smem);
    asm volatile("cp.async.cg.shared.global [%0], [%1], 16;" :: "r"(d), "l"(src));
}
#define CP_COMMIT() asm volatile("cp.async.commit_group;")
#define CP_WAIT(n)  asm volatile("cp.async.wait_group %0;" :: "n"(n))

__device__ __forceinline__ void ldsm_x4(unsigned r[4], const void* p) {
    unsigned a = (unsigned)__cvta_generic_to_shared(p);
    asm volatile("ldmatrix.sync.aligned.m8n8.x4.shared.b16 {%0,%1,%2,%3}, [%4];"
                 : "=r"(r[0]), "=r"(r[1]), "=r"(r[2]), "=r"(r[3]) : "r"(a));
}
__device__ __forceinline__ void ldsm_x4_t(unsigned r[4], const void* p) {
    unsigned a = (unsigned)__cvta_generic_to_shared(p);
    asm volatile("ldmatrix.sync.aligned.m8n8.x4.trans.shared.b16 {%0,%1,%2,%3}, [%4];"
                 : "=r"(r[0]), "=r"(r[1]), "=r"(r[2]), "=r"(r[3]) : "r"(a));
}

// ================= kernel 1: projections via 3xTF32 MMA (R10 verified) =================
#define WS_ST 132
__global__ void __maxnreg__(120) proj_kernel(
    const float* __restrict__ xq, const float* __restrict__ xk, const float* __restrict__ xv,
    const float* __restrict__ Wq, const float* __restrict__ bq,
    const float* __restrict__ Wk, const float* __restrict__ bk,
    const float* __restrict__ Wv, const float* __restrict__ bv)
{
    const int proj = blockIdx.z;
    const float* x; const float* W; const float* bias; __half* o;
    if (proj == 0)      { x = xq; W = Wq; bias = bq; o = g_q; }
    else if (proj == 1) { x = xk; W = Wk; bias = bk; o = g_k; }
    else                { x = xv; W = Wv; bias = bv; o = g_v; }

    const int row0 = blockIdx.x * 128;
    const int h0   = blockIdx.y * 128;

    __shared__ float xs_hi[128 * 20], xs_lo[128 * 20];
    __shared__ float ws_hi[16 * WS_ST], ws_lo[16 * WS_ST];

    const int tid = threadIdx.x;
    const int warp = tid >> 5, lane = tid & 31;
    const int wm = warp & 3, wn = warp >> 2;
    const int tg = lane & 3, gi = lane >> 2;

    float acc[2][8][4];
#pragma unroll
    for (int mi = 0; mi < 2; mi++)
#pragma unroll
        for (int ni = 0; ni < 8; ni++)
#pragma unroll
            for (int c = 0; c < 4; c++) acc[mi][ni][c] = 0.f;

    for (int kc = 0; kc < INDIM; kc += 16) {
#pragma unroll
        for (int i = 0; i < 2; i++) {
            int f4 = tid + i * 256;
            int r = f4 >> 2, c4 = (f4 & 3) * 4;
            float4 xv4 = *(const float4*)(x + (size_t)(row0 + r) * INDIM + kc + c4);
            float h0f, l0, h1, l1, h2, l2, h3, l3;
            split_tf32(xv4.x, h0f, l0); split_tf32(xv4.y, h1, l1);
            split_tf32(xv4.z, h2, l2); split_tf32(xv4.w, h3, l3);
            float* dh = xs_hi + r * 20 + c4;
            float* dl = xs_lo + r * 20 + c4;
            dh[0] = h0f; dh[1] = h1; dh[2] = h2; dh[3] = h3;
            dl[0] = l0;  dl[1] = l1; dl[2] = l2; dl[3] = l3;
        }
#pragma unroll
        for (int i = 0; i < 2; i++) {
            int f4 = tid + i * 256;
            int k = f4 >> 5, n4 = (f4 & 31) * 4;
            float4 wv4 = *(const float4*)(W + (size_t)(kc + k) * HID + h0 + n4);
            float h0f, l0, h1, l1, h2, l2, h3, l3;
            split_tf32(wv4.x, h0f, l0); split_tf32(wv4.y, h1, l1);
            split_tf32(wv4.z, h2, l2); split_tf32(wv4.w, h3, l3);
            *(float4*)(ws_hi + k * WS_ST + n4) = make_float4(h0f, h1, h2, h3);
            *(float4*)(ws_lo + k * WS_ST + n4) = make_float4(l0, l1, l2, l3);
        }
        __syncthreads();
#pragma unroll
        for (int ks = 0; ks < 16; ks += 8) {
            unsigned ah[2][4], al[2][4], bh[8][2], bl[8][2];
#pragma unroll
            for (int mi = 0; mi < 2; mi++) {
                int r = wm * 32 + mi * 16 + gi;
                ah[mi][0] = __float_as_uint(xs_hi[r * 20 + ks + tg]);
                ah[mi][1] = __float_as_uint(xs_hi[(r + 8) * 20 + ks + tg]);
                ah[mi][2] = __float_as_uint(xs_hi[r * 20 + ks + tg + 4]);
                ah[mi][3] = __float_as_uint(xs_hi[(r + 8) * 20 + ks + tg + 4]);
                al[mi][0] = __float_as_uint(xs_lo[r * 20 + ks + tg]);
                al[mi][1] = __float_as_uint(xs_lo[(r + 8) * 20 + ks + tg]);
                al[mi][2] = __float_as_uint(xs_lo[r * 20 + ks + tg + 4]);
                al[mi][3] = __float_as_uint(xs_lo[(r + 8) * 20 + ks + tg + 4]);
            }
#pragma unroll
            for (int ni = 0; ni < 8; ni++) {
                int n = wn * 64 + ni * 8 + gi;
                bh[ni][0] = __float_as_uint(ws_hi[(ks + tg) * WS_ST + n]);
                bh[ni][1] = __float_as_uint(ws_hi[(ks + tg + 4) * WS_ST + n]);
                bl[ni][0] = __float_as_uint(ws_lo[(ks + tg) * WS_ST + n]);
                bl[ni][1] = __float_as_uint(ws_lo[(ks + tg + 4) * WS_ST + n]);
            }
#pragma unroll
            for (int mi = 0; mi < 2; mi++)
#pragma unroll
                for (int ni = 0; ni < 8; ni++) {
                    mma_tf32(acc[mi][ni], ah[mi], bh[ni]);
                    mma_tf32(acc[mi][ni], ah[mi], bl[ni]);
                    mma_tf32(acc[mi][ni], al[mi], bh[ni]);
                }
        }
        __syncthreads();
    }
#pragma unroll
    for (int mi = 0; mi < 2; mi++) {
        int r0 = row0 + wm * 32 + mi * 16 + gi;
        int r1 = r0 + 8;
#pragma unroll
        for (int ni = 0; ni < 8; ni++) {
            int c = h0 + wn * 64 + ni * 8 + tg * 2;
            float2 bb = *(const float2*)(bias + c);
            *(__half2*)(o + (size_t)r0 * HID + c) =
                __float22half2_rn(make_float2(acc[mi][ni][0] + bb.x, acc[mi][ni][1] + bb.y));
            *(__half2*)(o + (size_t)r1 * HID + c) =
                __float22half2_rn(make_float2(acc[mi][ni][2] + bb.x, acc[mi][ni][3] + bb.y));
        }
    }
}

// ================= kernel 2: fused flash attention, K/V double-buffered =================
// Per iter: wait(K ready) -> B1 -> issue K[kt+1] -> S-MMA -> epilogue -> wait(V ready) -> B2
// -> issue V[kt+1] -> PV-MMA.  2 barriers/iter, fills overlap full MMA phases.
#define QT 64
#define KT 64
#define QKV_ST 264
#define PS_ST 72
#define Q_HALVES  (QT * QKV_ST)
#define KV_HALVES (KT * QKV_ST)
#define PS_HALVES (QT * PS_ST)
#define FUSED_SMEM_BYTES ((Q_HALVES + 4 * KV_HALVES + PS_HALVES) * 2 + (256 + 512) * 4)

__global__ void __maxnreg__(120) attn_kernel(
    const int* __restrict__ mask,
    const float* __restrict__ gamma,
    const float* __restrict__ beta,
    float* __restrict__ out)
{
    const int qt = blockIdx.x, b = blockIdx.y;
    extern __shared__ __half smh[];
    __half* Qs = smh;
    __half* Kbuf[2] = { Qs + Q_HALVES, Qs + Q_HALVES + KV_HALVES };
    __half* Vbuf[2] = { Qs + Q_HALVES + 2 * KV_HALVES, Qs + Q_HALVES + 3 * KV_HALVES };
    __half* Ps = Qs + Q_HALVES + 4 * KV_HALVES;
    float* rsum_sm = (float*)(Ps + PS_HALVES);
    float* rstat   = rsum_sm + 256;

    const int tid = threadIdx.x;
    const int warp = tid >> 5, lane = tid & 31;
    const int wm = warp & 1, wn = warp >> 1;
    const int tg = lane & 3, gi = lane >> 2;
    const int l15 = lane & 15, lhi = (lane >> 4) << 3;

    const __half* Qg = g_q + ((size_t)b * SEQ + qt * QT) * HID;
    const __half* Kg = g_k + (size_t)b * SEQ * HID;
    const __half* Vg = g_v + (size_t)b * SEQ * HID;
    const int* Mg = mask + ((size_t)b * SEQ + qt * QT) * SEQ;

    // per-thread fill coordinates (fixed): 64 rows x 32 granules, 8 chunks/thread
    const int fr = tid >> 5;              // rows fr, fr+8, ..., fr+56
    const int fg = (tid & 31) * 8;        // granule offset in halves

    float accO[2][8][4];
#pragma unroll
    for (int mi = 0; mi < 2; mi++)
#pragma unroll
        for (int ni = 0; ni < 8; ni++)
#pragma unroll
            for (int c = 0; c < 4; c++) accO[mi][ni][c] = 0.f;
    float rs[2][2] = {{0.f, 0.f}, {0.f, 0.f}};

    // prologue: {Q, K0} commit, {V0} commit
#pragma unroll
    for (int i = 0; i < 8; i++) {
        cpa16(Qs + (fr + i * 8) * QKV_ST + fg, Qg + (size_t)(fr + i * 8) * HID + fg);
        cpa16(Kbuf[0] + (fr + i * 8) * QKV_ST + fg, Kg + (size_t)(fr + i * 8) * HID + fg);
    }
    CP_COMMIT();
#pragma unroll
    for (int i = 0; i < 8; i++)
        cpa16(Vbuf[0] + (fr + i * 8) * QKV_ST + fg, Vg + (size_t)(fr + i * 8) * HID + fg);
    CP_COMMIT();

    const int NKT2 = SEQ / KT;   // 32
    for (int kt = 0; kt < NKT2; kt++) {
        const int cur = kt & 1, nxt = cur ^ 1;
        // mask prefetch (LDG in flight through S-MMA)
        int2 mreg[8];
#pragma unroll
        for (int mi = 0; mi < 2; mi++)
#pragma unroll
            for (int ni = 0; ni < 2; ni++) {
                int r0 = wm * 32 + mi * 16 + gi;
                int c0 = wn * 16 + ni * 8 + tg * 2;
                mreg[(mi * 2 + ni) * 2 + 0] = *(const int2*)(Mg + (size_t)r0 * SEQ + kt * KT + c0);
                mreg[(mi * 2 + ni) * 2 + 1] = *(const int2*)(Mg + (size_t)(r0 + 8) * SEQ + kt * KT + c0);
            }

        CP_WAIT(1);                 // K[kt] (and all older) landed; newest (V[kt] or K-fill) may pend
        __syncthreads();            // B1: K[kt] visible; prev PV reads of Vbuf[nxt] done

        if (kt + 1 < NKT2) {        // K[kt+1] -> Kbuf[nxt] (last read before prev B2 < B1)
            const __half* kp = Kg + (size_t)(kt + 1) * KT * HID;
#pragma unroll
            for (int i = 0; i < 8; i++)
                cpa16(Kbuf[nxt] + (fr + i * 8) * QKV_ST + fg, kp + (size_t)(fr + i * 8) * HID + fg);
            CP_COMMIT();
        }

        // ---- S = Q K^T over K=256 ----
        float accS[2][2][4];
#pragma unroll
        for (int mi = 0; mi < 2; mi++)
#pragma unroll
            for (int ni = 0; ni < 2; ni++)
#pragma unroll
                for (int c = 0; c < 4; c++) accS[mi][ni][c] = 0.f;
        const __half* Kc = Kbuf[cur];
#pragma unroll
        for (int ks = 0; ks < HID; ks += 16) {
            unsigned a[2][4], bb[4];
            ldsm_x4(a[0], Qs + (wm * 32 + l15) * QKV_ST + ks + lhi);
            ldsm_x4(a[1], Qs + (wm * 32 + 16 + l15) * QKV_ST + ks + lhi);
            ldsm_x4(bb,   Kc + (wn * 16 + l15) * QKV_ST + ks + lhi);
            mma_f16(accS[0][0], a[0], bb[0], bb[2]);
            mma_f16(accS[0][1], a[0], bb[1], bb[3]);
            mma_f16(accS[1][0], a[1], bb[0], bb[2]);
            mma_f16(accS[1][1], a[1], bb[1], bb[3]);
        }

        // ---- epilogue: mask, exp, rowsum, Ps ----
        const float scale = 0.0625f;
#pragma unroll
        for (int mi = 0; mi < 2; mi++) {
            int r0 = wm * 32 + mi * 16 + gi;
            int r1 = r0 + 8;
#pragma unroll
            for (int ni = 0; ni < 2; ni++) {
                int c0 = wn * 16 + ni * 8 + tg * 2;
                int2 m0 = mreg[(mi * 2 + ni) * 2 + 0];
                int2 m1 = mreg[(mi * 2 + ni) * 2 + 1];
                float p00 = m0.x ? __expf(accS[mi][ni][0] * scale) : 0.f;
                float p01 = m0.y ? __expf(accS[mi][ni][1] * scale) : 0.f;
                float p10 = m1.x ? __expf(accS[mi][ni][2] * scale) : 0.f;
                float p11 = m1.y ? __expf(accS[mi][ni][3] * scale) : 0.f;
                rs[mi][0] += p00 + p01;
                rs[mi][1] += p10 + p11;
                *(__half2*)(Ps + r0 * PS_ST + c0) = __float22half2_rn(make_float2(p00, p01));
                *(__half2*)(Ps + r1 * PS_ST + c0) = __float22half2_rn(make_float2(p10, p11));
            }
        }

        if (kt + 1 < NKT2) { CP_WAIT(1); } else { CP_WAIT(0); }   // V[kt] landed (K[kt+1] may pend)
        __syncthreads();            // B2: Ps + V[kt] visible; all S-reads of Kbuf[cur] done

        if (kt + 1 < NKT2) {        // V[kt+1] -> Vbuf[nxt] (last read before B1 this iter)
            const __half* vp = Vg + (size_t)(kt + 1) * KT * HID;
#pragma unroll
            for (int i = 0; i < 8; i++)
                cpa16(Vbuf[nxt] + (fr + i * 8) * QKV_ST + fg, vp + (size_t)(fr + i * 8) * HID + fg);
            CP_COMMIT();
        }

        // ---- O += Ps V ----
        const __half* Vc = Vbuf[cur];
#pragma unroll
        for (int ks = 0; ks < KT; ks += 16) {
            unsigned a[2][4], bb[4][4];
#pragma unroll
            for (int mi = 0; mi < 2; mi++)
                ldsm_x4(a[mi], Ps + (wm * 32 + mi * 16 + l15) * PS_ST + ks + lhi);
#pragma unroll
            for (int nj = 0; nj < 4; nj++)
                ldsm_x4_t(bb[nj], Vc + (size_t)(ks + l15) * QKV_ST + wn * 64 + nj * 16 + lhi);
#pragma unroll
            for (int mi = 0; mi < 2; mi++)
#pragma unroll
                for (int nj = 0; nj < 4; nj++) {
                    mma_f16(accO[mi][nj * 2],     a[mi], bb[nj][0], bb[nj][1]);
                    mma_f16(accO[mi][nj * 2 + 1], a[mi], bb[nj][2], bb[nj][3]);
                }
        }
    }

    // ---- rowsum cross-warp reduction ----
#pragma unroll
    for (int mi = 0; mi < 2; mi++) {
#pragma unroll
        for (int h = 0; h < 2; h++) {
            float v = rs[mi][h];
            v += __shfl_xor_sync(0xffffffffu, v, 1);
            v += __shfl_xor_sync(0xffffffffu, v, 2);
            rs[mi][h] = v;
        }
        if (tg == 0) {
            int rl = wm * 32 + mi * 16 + gi;
            rsum_sm[wn * 64 + rl]     = rs[mi][0];
            rsum_sm[wn * 64 + rl + 8] = rs[mi][1];
        }
    }
    __syncthreads();

    // ---- normalize + per-row sum/sumsq ----
#pragma unroll
    for (int mi = 0; mi < 2; mi++) {
        int rl0 = wm * 32 + mi * 16 + gi;
        int rl1 = rl0 + 8;
        float t0 = rsum_sm[rl0] + rsum_sm[64 + rl0] + rsum_sm[128 + rl0] + rsum_sm[192 + rl0];
        float t1 = rsum_sm[rl1] + rsum_sm[64 + rl1] + rsum_sm[128 + rl1] + rsum_sm[192 + rl1];
        float i0 = 1.f / t0, i1 = 1.f / t1;
        float s0 = 0.f, s1 = 0.f, q0 = 0.f, q1 = 0.f;
#pragma unroll
        for (int ni = 0; ni < 8; ni++) {
            float v00 = accO[mi][ni][0] * i0; accO[mi][ni][0] = v00;
            float v01 = accO[mi][ni][1] * i0; accO[mi][ni][1] = v01;
            float v10 = accO[mi][ni][2] * i1; accO[mi][ni][2] = v10;
            float v11 = accO[mi][ni][3] * i1; accO[mi][ni][3] = v11;
            s0 += v00 + v01; s1 += v10 + v11;
            q0 += v00 * v00 + v01 * v01;
            q1 += v10 * v10 + v11 * v11;
        }
        s0 += __shfl_xor_sync(0xffffffffu, s0, 1); s0 += __shfl_xor_sync(0xffffffffu, s0, 2);
        s1 += __shfl_xor_sync(0xffffffffu, s1, 1); s1 += __shfl_xor_sync(0xffffffffu, s1, 2);
        q0 += __shfl_xor_sync(0xffffffffu, q0, 1); q0 += __shfl_xor_sync(0xffffffffu, q0, 2);
        q1 += __shfl_xor_sync(0xffffffffu, q1, 1); q1 += __shfl_xor_sync(0xffffffffu, q1, 2);
        if (tg == 0) {
            rstat[wn * 128 + rl0 * 2]     = s0;
            rstat[wn * 128 + rl0 * 2 + 1] = q0;
            rstat[wn * 128 + rl1 * 2]     = s1;
            rstat[wn * 128 + rl1 * 2 + 1] = q1;
        }
    }
    __syncthreads();

    // ---- LayerNorm + write ----
#pragma unroll
    for (int mi = 0; mi < 2; mi++) {
        int rl0 = wm * 32 + mi * 16 + gi;
        int rl1 = rl0 + 8;
        float sum0 = rstat[rl0*2] + rstat[128 + rl0*2] + rstat[256 + rl0*2] + rstat[384 + rl0*2];
        float sq0  = rstat[rl0*2+1] + rstat[128 + rl0*2+1] + rstat[256 + rl0*2+1] + rstat[384 + rl0*2+1];
        float sum1 = rstat[rl1*2] + rstat[128 + rl1*2] + rstat[256 + rl1*2] + rstat[384 + rl1*2];
        float sq1  = rstat[rl1*2+1] + rstat[128 + rl1*2+1] + rstat[256 + rl1*2+1] + rstat[384 + rl1*2+1];
        float mu0 = sum0 * (1.f / HID);
        float mu1 = sum1 * (1.f / HID);
        float var0 = sq0 * (1.f / HID) - mu0 * mu0;
        float var1 = sq1 * (1.f / HID) - mu1 * mu1;
        float rstd0 = rsqrtf(var0 + 1e-6f);
        float rstd1 = rsqrtf(var1 + 1e-6f);
        size_t orow0 = ((size_t)b * SEQ + qt * QT + rl0) * HID;
        size_t orow1 = ((size_t)b * SEQ + qt * QT + rl1) * HID;
#pragma unroll
        for (int ni = 0; ni < 8; ni++) {
            int c0 = wn * 64 + ni * 8 + tg * 2;
            float2 gm = *(const float2*)(gamma + c0);
            float2 bt = *(const float2*)(beta + c0);
            float2 o0, o1;
            o0.x = (accO[mi][ni][0] - mu0) * rstd0 * gm.x + bt.x;
            o0.y = (accO[mi][ni][1] - mu0) * rstd0 * gm.y + bt.y;
            o1.x = (accO[mi][ni][2] - mu1) * rstd1 * gm.x + bt.x;
            o1.y = (accO[mi][ni][3] - mu1) * rstd1 * gm.y + bt.y;
            *(float2*)(out + orow0 + c0) = o0;
            *(float2*)(out + orow1 + c0) = o1;
        }
    }
}

// ---------------- launch ----------------
extern "C" void kernel_launch(void* const* d_in, const int* in_sizes, int n_in,
                              void* d_out, int out_size)
{
    const float* q     = (const float*)d_in[0];
    const float* k     = (const float*)d_in[1];
    const float* v     = (const float*)d_in[2];
    const int*   mask  = (const int*)  d_in[3];
    const float* Wq    = (const float*)d_in[4];
    const float* bq    = (const float*)d_in[5];
    const float* Wk    = (const float*)d_in[6];
    const float* bk    = (const float*)d_in[7];
    const float* Wv    = (const float*)d_in[8];
    const float* bv    = (const float*)d_in[9];
    const float* gamma = (const float*)d_in[10];
    const float* beta  = (const float*)d_in[11];
    float* out = (float*)d_out;

    static int inited = 0;
    if (!inited) {
        cudaFuncSetAttribute(attn_kernel, cudaFuncAttributeMaxDynamicSharedMemorySize, FUSED_SMEM_BYTES);
        inited = 1;
    }

    dim3 gp(BATCH * SEQ / 128, HID / 128, 3);
    proj_kernel<<<gp, 256>>>(q, k, v, Wq, bq, Wk, bk, Wv, bv);

    dim3 ga(SEQ / QT, BATCH);
    attn_kernel<<<ga, 256, FUSED_SMEM_BYTES>>>(mask, gamma, beta, out);
}

// round 15
// speedup vs baseline: 1.2923x; 1.2923x over previous
#include <cuda_runtime.h>
#include <cuda_fp16.h>
#include <cstdint>
#include <cstddef>

#define BATCH 8
#define SEQ   2048
#define HID   256
#define INDIM 96

// ---------------- scratch ----------------
__device__ __align__(256) __half g_q[BATCH * SEQ * HID];
__device__ __align__(256) __half g_k[BATCH * SEQ * HID];
__device__ __align__(256) __half g_v[BATCH * SEQ * HID];

// ---------------- helpers ----------------
__device__ __forceinline__ unsigned f2tf32(float x) {
    unsigned r;
    asm("cvt.rna.tf32.f32 %0, %1;" : "=r"(r) : "f"(x));
    return r;
}
__device__ __forceinline__ void split_tf32(float x, float& hi, float& lo) {
    hi = __uint_as_float(f2tf32(x));
    lo = __uint_as_float(f2tf32(x - hi));
}
__device__ __forceinline__ void mma_tf32(float c[4], const unsigned a[4], const unsigned b[2]) {
    asm("mma.sync.aligned.m16n8k8.row.col.f32.tf32.tf32.f32 "
        "{%0,%1,%2,%3}, {%4,%5,%6,%7}, {%8,%9}, {%0,%1,%2,%3};\n"
        : "+f"(c[0]), "+f"(c[1]), "+f"(c[2]), "+f"(c[3])
        : "r"(a[0]), "r"(a[1]), "r"(a[2]), "r"(a[3]), "r"(b[0]), "r"(b[1]));
}
__device__ __forceinline__ void mma_f16(float c[4], const unsigned a[4], unsigned b0, unsigned b1) {
    asm("mma.sync.aligned.m16n8k16.row.col.f32.f16.f16.f32 "
        "{%0,%1,%2,%3}, {%4,%5,%6,%7}, {%8,%9}, {%0,%1,%2,%3};\n"
        : "+f"(c[0]), "+f"(c[1]), "+f"(c[2]), "+f"(c[3])
        : "r"(a[0]), "r"(a[1]), "r"(a[2]), "r"(a[3]), "r"(b0), "r"(b1));
}
__device__ __forceinline__ void cpa16(void* dst_smem, const void* src) {
    unsigned d = (unsigned)__cvta_generic_to_shared(dst_smem);
    asm volatile("cp.async.cg.shared.global [%0], [%1], 16;" :: "r"(d), "l"(src));
}
#define CP_COMMIT() asm volatile("cp.async.commit_group;")
#define CP_WAIT(n)  asm volatile("cp.async.wait_group %0;" :: "n"(n))

__device__ __forceinline__ void ldsm_x4(unsigned r[4], const void* p) {
    unsigned a = (unsigned)__cvta_generic_to_shared(p);
    asm volatile("ldmatrix.sync.aligned.m8n8.x4.shared.b16 {%0,%1,%2,%3}, [%4];"
                 : "=r"(r[0]), "=r"(r[1]), "=r"(r[2]), "=r"(r[3]) : "r"(a));
}
__device__ __forceinline__ void ldsm_x4_t(unsigned r[4], const void* p) {
    unsigned a = (unsigned)__cvta_generic_to_shared(p);
    asm volatile("ldmatrix.sync.aligned.m8n8.x4.trans.shared.b16 {%0,%1,%2,%3}, [%4];"
                 : "=r"(r[0]), "=r"(r[1]), "=r"(r[2]), "=r"(r[3]) : "r"(a));
}

// ================= kernel 1: projections via 3xTF32 MMA (verified) =================
#define WS_ST 132
__global__ void __maxnreg__(120) proj_kernel(
    const float* __restrict__ xq, const float* __restrict__ xk, const float* __restrict__ xv,
    const float* __restrict__ Wq, const float* __restrict__ bq,
    const float* __restrict__ Wk, const float* __restrict__ bk,
    const float* __restrict__ Wv, const float* __restrict__ bv)
{
    const int proj = blockIdx.z;
    const float* x; const float* W; const float* bias; __half* o;
    if (proj == 0)      { x = xq; W = Wq; bias = bq; o = g_q; }
    else if (proj == 1) { x = xk; W = Wk; bias = bk; o = g_k; }
    else                { x = xv; W = Wv; bias = bv; o = g_v; }

    const int row0 = blockIdx.x * 128;
    const int h0   = blockIdx.y * 128;

    __shared__ float xs_hi[128 * 20], xs_lo[128 * 20];
    __shared__ float ws_hi[16 * WS_ST], ws_lo[16 * WS_ST];

    const int tid = threadIdx.x;
    const int warp = tid >> 5, lane = tid & 31;
    const int wm = warp & 3, wn = warp >> 2;
    const int tg = lane & 3, gi = lane >> 2;

    float acc[2][8][4];
#pragma unroll
    for (int mi = 0; mi < 2; mi++)
#pragma unroll
        for (int ni = 0; ni < 8; ni++)
#pragma unroll
            for (int c = 0; c < 4; c++) acc[mi][ni][c] = 0.f;

    for (int kc = 0; kc < INDIM; kc += 16) {
#pragma unroll
        for (int i = 0; i < 2; i++) {
            int f4 = tid + i * 256;
            int r = f4 >> 2, c4 = (f4 & 3) * 4;
            float4 xv4 = *(const float4*)(x + (size_t)(row0 + r) * INDIM + kc + c4);
            float h0f, l0, h1, l1, h2, l2, h3, l3;
            split_tf32(xv4.x, h0f, l0); split_tf32(xv4.y, h1, l1);
            split_tf32(xv4.z, h2, l2); split_tf32(xv4.w, h3, l3);
            float* dh = xs_hi + r * 20 + c4;
            float* dl = xs_lo + r * 20 + c4;
            dh[0] = h0f; dh[1] = h1; dh[2] = h2; dh[3] = h3;
            dl[0] = l0;  dl[1] = l1; dl[2] = l2; dl[3] = l3;
        }
#pragma unroll
        for (int i = 0; i < 2; i++) {
            int f4 = tid + i * 256;
            int k = f4 >> 5, n4 = (f4 & 31) * 4;
            float4 wv4 = *(const float4*)(W + (size_t)(kc + k) * HID + h0 + n4);
            float h0f, l0, h1, l1, h2, l2, h3, l3;
            split_tf32(wv4.x, h0f, l0); split_tf32(wv4.y, h1, l1);
            split_tf32(wv4.z, h2, l2); split_tf32(wv4.w, h3, l3);
            *(float4*)(ws_hi + k * WS_ST + n4) = make_float4(h0f, h1, h2, h3);
            *(float4*)(ws_lo + k * WS_ST + n4) = make_float4(l0, l1, l2, l3);
        }
        __syncthreads();
#pragma unroll
        for (int ks = 0; ks < 16; ks += 8) {
            unsigned ah[2][4], al[2][4], bh[8][2], bl[8][2];
#pragma unroll
            for (int mi = 0; mi < 2; mi++) {
                int r = wm * 32 + mi * 16 + gi;
                ah[mi][0] = __float_as_uint(xs_hi[r * 20 + ks + tg]);
                ah[mi][1] = __float_as_uint(xs_hi[(r + 8) * 20 + ks + tg]);
                ah[mi][2] = __float_as_uint(xs_hi[r * 20 + ks + tg + 4]);
                ah[mi][3] = __float_as_uint(xs_hi[(r + 8) * 20 + ks + tg + 4]);
                al[mi][0] = __float_as_uint(xs_lo[r * 20 + ks + tg]);
                al[mi][1] = __float_as_uint(xs_lo[(r + 8) * 20 + ks + tg]);
                al[mi][2] = __float_as_uint(xs_lo[r * 20 + ks + tg + 4]);
                al[mi][3] = __float_as_uint(xs_lo[(r + 8) * 20 + ks + tg + 4]);
            }
#pragma unroll
            for (int ni = 0; ni < 8; ni++) {
                int n = wn * 64 + ni * 8 + gi;
                bh[ni][0] = __float_as_uint(ws_hi[(ks + tg) * WS_ST + n]);
                bh[ni][1] = __float_as_uint(ws_hi[(ks + tg + 4) * WS_ST + n]);
                bl[ni][0] = __float_as_uint(ws_lo[(ks + tg) * WS_ST + n]);
                bl[ni][1] = __float_as_uint(ws_lo[(ks + tg + 4) * WS_ST + n]);
            }
#pragma unroll
            for (int mi = 0; mi < 2; mi++)
#pragma unroll
                for (int ni = 0; ni < 8; ni++) {
                    mma_tf32(acc[mi][ni], ah[mi], bh[ni]);
                    mma_tf32(acc[mi][ni], ah[mi], bl[ni]);
                    mma_tf32(acc[mi][ni], al[mi], bh[ni]);
                }
        }
        __syncthreads();
    }
#pragma unroll
    for (int mi = 0; mi < 2; mi++) {
        int r0 = row0 + wm * 32 + mi * 16 + gi;
        int r1 = r0 + 8;
#pragma unroll
        for (int ni = 0; ni < 8; ni++) {
            int c = h0 + wn * 64 + ni * 8 + tg * 2;
            float2 bb = *(const float2*)(bias + c);
            *(__half2*)(o + (size_t)r0 * HID + c) =
                __float22half2_rn(make_float2(acc[mi][ni][0] + bb.x, acc[mi][ni][1] + bb.y));
            *(__half2*)(o + (size_t)r1 * HID + c) =
                __float22half2_rn(make_float2(acc[mi][ni][2] + bb.x, acc[mi][ni][3] + bb.y));
        }
    }
}

// ================= kernel 2: fused flash attention, KT=32, K/V double-buffered =================
// smem ~107 KB -> 2 CTAs/SM.  Per iter: wait(K)->B1->issue K[+1]->S-MMA(4x4 warp map)
// ->epilogue->wait(V)->B2->issue V[+1]->PV-MMA(2x4 warp map).
#define QT 64
#define KT 32
#define QKV_ST 264
#define PS_ST 40
#define Q_HALVES  (QT * QKV_ST)
#define K_HALVES  (KT * QKV_ST)
#define PS_HALVES (QT * PS_ST)
#define FUSED_SMEM_BYTES ((Q_HALVES + 4 * K_HALVES + PS_HALVES) * 2 + (256 + 512) * 4)

__global__ void __maxnreg__(120) attn_kernel(
    const int* __restrict__ mask,
    const float* __restrict__ gamma,
    const float* __restrict__ beta,
    float* __restrict__ out)
{
    const int qt = blockIdx.x, b = blockIdx.y;
    extern __shared__ __half smh[];
    __half* Qs = smh;
    __half* Kbuf[2] = { Qs + Q_HALVES, Qs + Q_HALVES + K_HALVES };
    __half* Vbuf[2] = { Qs + Q_HALVES + 2 * K_HALVES, Qs + Q_HALVES + 3 * K_HALVES };
    __half* Ps = Qs + Q_HALVES + 4 * K_HALVES;
    float* rsum_sm = (float*)(Ps + PS_HALVES);   // 2 x 64 used
    float* rstat   = rsum_sm + 256;              // 4 x 64 x 2

    const int tid = threadIdx.x;
    const int warp = tid >> 5, lane = tid & 31;
    const int wm  = warp & 1, wn  = warp >> 1;   // PV mapping: 2x32 rows, 4x64 cols
    const int wm2 = warp & 3, wn2 = warp >> 2;   // S mapping: 4x16 rows, 2x16 cols
    const int tg = lane & 3, gi = lane >> 2;
    const int l15 = lane & 15, lhi = (lane >> 4) << 3;

    const __half* Qg = g_q + ((size_t)b * SEQ + qt * QT) * HID;
    const __half* Kg = g_k + (size_t)b * SEQ * HID;
    const __half* Vg = g_v + (size_t)b * SEQ * HID;
    const int* Mg = mask + ((size_t)b * SEQ + qt * QT) * SEQ;

    // fill coords: K/V tile 32 rows x 32 granules = 1024 chunks, 4/thread
    const int fr = tid >> 5;              // rows fr + i*8, i<4
    const int fg = (tid & 31) * 8;

    float accO[2][8][4];
#pragma unroll
    for (int mi = 0; mi < 2; mi++)
#pragma unroll
        for (int ni = 0; ni < 8; ni++)
#pragma unroll
            for (int c = 0; c < 4; c++) accO[mi][ni][c] = 0.f;
    float rs[2] = {0.f, 0.f};             // rows wm2*16+gi, +8

    // prologue: {Q, K0} commit; {V0} commit
#pragma unroll
    for (int i = 0; i < 8; i++)
        cpa16(Qs + (fr + i * 8) * QKV_ST + fg, Qg + (size_t)(fr + i * 8) * HID + fg);
#pragma unroll
    for (int i = 0; i < 4; i++)
        cpa16(Kbuf[0] + (fr + i * 8) * QKV_ST + fg, Kg + (size_t)(fr + i * 8) * HID + fg);
    CP_COMMIT();
#pragma unroll
    for (int i = 0; i < 4; i++)
        cpa16(Vbuf[0] + (fr + i * 8) * QKV_ST + fg, Vg + (size_t)(fr + i * 8) * HID + fg);
    CP_COMMIT();

    const int NKT2 = SEQ / KT;   // 64
    for (int kt = 0; kt < NKT2; kt++) {
        const int cur = kt & 1, nxt = cur ^ 1;
        // mask prefetch: S tile rows wm2*16+gi(+8), cols wn2*16 + ni*8 + tg*2
        int2 mreg[4];
        {
            int r0 = wm2 * 16 + gi;
#pragma unroll
            for (int ni = 0; ni < 2; ni++) {
                int c0 = wn2 * 16 + ni * 8 + tg * 2;
                mreg[ni * 2 + 0] = *(const int2*)(Mg + (size_t)r0 * SEQ + kt * KT + c0);
                mreg[ni * 2 + 1] = *(const int2*)(Mg + (size_t)(r0 + 8) * SEQ + kt * KT + c0);
            }
        }

        CP_WAIT(1);                 // K[kt] landed (V[kt] may pend)
        __syncthreads();            // B1: K[kt] visible; PV(kt-1) reads of Vbuf[nxt], Ps done

        if (kt + 1 < NKT2) {        // K[kt+1] -> Kbuf[nxt]
            const __half* kp = Kg + (size_t)(kt + 1) * KT * HID;
#pragma unroll
            for (int i = 0; i < 4; i++)
                cpa16(Kbuf[nxt] + (fr + i * 8) * QKV_ST + fg, kp + (size_t)(fr + i * 8) * HID + fg);
            CP_COMMIT();
        }

        // ---- S = Q K^T over K=256 (warp: 16 rows x 16 cols) ----
        float accS[2][4];
#pragma unroll
        for (int ni = 0; ni < 2; ni++)
#pragma unroll
            for (int c = 0; c < 4; c++) accS[ni][c] = 0.f;
        const __half* Kc = Kbuf[cur];
#pragma unroll
        for (int ks = 0; ks < HID; ks += 16) {
            unsigned a[4], bb[4];
            ldsm_x4(a,  Qs + (wm2 * 16 + l15) * QKV_ST + ks + lhi);
            ldsm_x4(bb, Kc + (wn2 * 16 + l15) * QKV_ST + ks + lhi);
            mma_f16(accS[0], a, bb[0], bb[2]);
            mma_f16(accS[1], a, bb[1], bb[3]);
        }

        // ---- epilogue: mask, exp, rowsum, Ps ----
        const float scale = 0.0625f;
        {
            int r0 = wm2 * 16 + gi;
            int r1 = r0 + 8;
#pragma unroll
            for (int ni = 0; ni < 2; ni++) {
                int c0 = wn2 * 16 + ni * 8 + tg * 2;
                int2 m0 = mreg[ni * 2 + 0];
                int2 m1 = mreg[ni * 2 + 1];
                float p00 = m0.x ? __expf(accS[ni][0] * scale) : 0.f;
                float p01 = m0.y ? __expf(accS[ni][1] * scale) : 0.f;
                float p10 = m1.x ? __expf(accS[ni][2] * scale) : 0.f;
                float p11 = m1.y ? __expf(accS[ni][3] * scale) : 0.f;
                rs[0] += p00 + p01;
                rs[1] += p10 + p11;
                *(__half2*)(Ps + r0 * PS_ST + c0) = __float22half2_rn(make_float2(p00, p01));
                *(__half2*)(Ps + r1 * PS_ST + c0) = __float22half2_rn(make_float2(p10, p11));
            }
        }

        if (kt + 1 < NKT2) { CP_WAIT(1); } else { CP_WAIT(0); }   // V[kt] landed
        __syncthreads();            // B2: Ps + V[kt] visible; S reads of Kbuf[cur] done

        if (kt + 1 < NKT2) {        // V[kt+1] -> Vbuf[nxt]
            const __half* vp = Vg + (size_t)(kt + 1) * KT * HID;
#pragma unroll
            for (int i = 0; i < 4; i++)
                cpa16(Vbuf[nxt] + (fr + i * 8) * QKV_ST + fg, vp + (size_t)(fr + i * 8) * HID + fg);
            CP_COMMIT();
        }

        // ---- O += Ps V (warp: 32 rows x 64 cols) ----
        const __half* Vc = Vbuf[cur];
#pragma unroll
        for (int ks = 0; ks < KT; ks += 16) {
            unsigned a[2][4], bb[4][4];
#pragma unroll
            for (int mi = 0; mi < 2; mi++)
                ldsm_x4(a[mi], Ps + (wm * 32 + mi * 16 + l15) * PS_ST + ks + lhi);
#pragma unroll
            for (int nj = 0; nj < 4; nj++)
                ldsm_x4_t(bb[nj], Vc + (size_t)(ks + l15) * QKV_ST + wn * 64 + nj * 16 + lhi);
#pragma unroll
            for (int mi = 0; mi < 2; mi++)
#pragma unroll
                for (int nj = 0; nj < 4; nj++) {
                    mma_f16(accO[mi][nj * 2],     a[mi], bb[nj][0], bb[nj][1]);
                    mma_f16(accO[mi][nj * 2 + 1], a[mi], bb[nj][2], bb[nj][3]);
                }
        }
    }

    // ---- rowsum cross-warp reduction (2 partials: wn2 groups) ----
#pragma unroll
    for (int h = 0; h < 2; h++) {
        float v = rs[h];
        v += __shfl_xor_sync(0xffffffffu, v, 1);
        v += __shfl_xor_sync(0xffffffffu, v, 2);
        rs[h] = v;
    }
    if (tg == 0) {
        int rl = wm2 * 16 + gi;
        rsum_sm[wn2 * 64 + rl]     = rs[0];
        rsum_sm[wn2 * 64 + rl + 8] = rs[1];
    }
    __syncthreads();

    // ---- normalize + per-row sum/sumsq (PV mapping) ----
#pragma unroll
    for (int mi = 0; mi < 2; mi++) {
        int rl0 = wm * 32 + mi * 16 + gi;
        int rl1 = rl0 + 8;
        float t0 = rsum_sm[rl0] + rsum_sm[64 + rl0];
        float t1 = rsum_sm[rl1] + rsum_sm[64 + rl1];
        float i0 = 1.f / t0, i1 = 1.f / t1;
        float s0 = 0.f, s1 = 0.f, q0 = 0.f, q1 = 0.f;
#pragma unroll
        for (int ni = 0; ni < 8; ni++) {
            float v00 = accO[mi][ni][0] * i0; accO[mi][ni][0] = v00;
            float v01 = accO[mi][ni][1] * i0; accO[mi][ni][1] = v01;
            float v10 = accO[mi][ni][2] * i1; accO[mi][ni][2] = v10;
            float v11 = accO[mi][ni][3] * i1; accO[mi][ni][3] = v11;
            s0 += v00 + v01; s1 += v10 + v11;
            q0 += v00 * v00 + v01 * v01;
            q1 += v10 * v10 + v11 * v11;
        }
        s0 += __shfl_xor_sync(0xffffffffu, s0, 1); s0 += __shfl_xor_sync(0xffffffffu, s0, 2);
        s1 += __shfl_xor_sync(0xffffffffu, s1, 1); s1 += __shfl_xor_sync(0xffffffffu, s1, 2);
        q0 += __shfl_xor_sync(0xffffffffu, q0, 1); q0 += __shfl_xor_sync(0xffffffffu, q0, 2);
        q1 += __shfl_xor_sync(0xffffffffu, q1, 1); q1 += __shfl_xor_sync(0xffffffffu, q1, 2);
        if (tg == 0) {
            rstat[wn * 128 + rl0 * 2]     = s0;
            rstat[wn * 128 + rl0 * 2 + 1] = q0;
            rstat[wn * 128 + rl1 * 2]     = s1;
            rstat[wn * 128 + rl1 * 2 + 1] = q1;
        }
    }
    __syncthreads();

    // ---- LayerNorm + write ----
#pragma unroll
    for (int mi = 0; mi < 2; mi++) {
        int rl0 = wm * 32 + mi * 16 + gi;
        int rl1 = rl0 + 8;
        float sum0 = rstat[rl0*2] + rstat[128 + rl0*2] + rstat[256 + rl0*2] + rstat[384 + rl0*2];
        float sq0  = rstat[rl0*2+1] + rstat[128 + rl0*2+1] + rstat[256 + rl0*2+1] + rstat[384 + rl0*2+1];
        float sum1 = rstat[rl1*2] + rstat[128 + rl1*2] + rstat[256 + rl1*2] + rstat[384 + rl1*2];
        float sq1  = rstat[rl1*2+1] + rstat[128 + rl1*2+1] + rstat[256 + rl1*2+1] + rstat[384 + rl1*2+1];
        float mu0 = sum0 * (1.f / HID);
        float mu1 = sum1 * (1.f / HID);
        float var0 = sq0 * (1.f / HID) - mu0 * mu0;
        float var1 = sq1 * (1.f / HID) - mu1 * mu1;
        float rstd0 = rsqrtf(var0 + 1e-6f);
        float rstd1 = rsqrtf(var1 + 1e-6f);
        size_t orow0 = ((size_t)b * SEQ + qt * QT + rl0) * HID;
        size_t orow1 = ((size_t)b * SEQ + qt * QT + rl1) * HID;
#pragma unroll
        for (int ni = 0; ni < 8; ni++) {
            int c0 = wn * 64 + ni * 8 + tg * 2;
            float2 gm = *(const float2*)(gamma + c0);
            float2 bt = *(const float2*)(beta + c0);
            float2 o0, o1;
            o0.x = (accO[mi][ni][0] - mu0) * rstd0 * gm.x + bt.x;
            o0.y = (accO[mi][ni][1] - mu0) * rstd0 * gm.y + bt.y;
            o1.x = (accO[mi][ni][2] - mu1) * rstd1 * gm.x + bt.x;
            o1.y = (accO[mi][ni][3] - mu1) * rstd1 * gm.y + bt.y;
            *(float2*)(out + orow0 + c0) = o0;
            *(float2*)(out + orow1 + c0) = o1;
        }
    }
}

// ---------------- launch ----------------
extern "C" void kernel_launch(void* const* d_in, const int* in_sizes, int n_in,
                              void* d_out, int out_size)
{
    const float* q     = (const float*)d_in[0];
    const float* k     = (const float*)d_in[1];
    const float* v     = (const float*)d_in[2];
    const int*   mask  = (const int*)  d_in[3];
    const float* Wq    = (const float*)d_in[4];
    const float* bq    = (const float*)d_in[5];
    const float* Wk    = (const float*)d_in[6];
    const float* bk    = (const float*)d_in[7];
    const float* Wv    = (const float*)d_in[8];
    const float* bv    = (const float*)d_in[9];
    const float* gamma = (const float*)d_in[10];
    const float* beta  = (const float*)d_in[11];
    float* out = (float*)d_out;

    static int inited = 0;
    if (!inited) {
        cudaFuncSetAttribute(attn_kernel, cudaFuncAttributeMaxDynamicSharedMemorySize, FUSED_SMEM_BYTES);
        inited = 1;
    }

    dim3 gp(BATCH * SEQ / 128, HID / 128, 3);
    proj_kernel<<<gp, 256>>>(q, k, v, Wq, bq, Wk, bk, Wv, bv);

    dim3 ga(SEQ / QT, BATCH);
    attn_kernel<<<ga, 256, FUSED_SMEM_BYTES>>>(mask, gamma, beta, out);
}

// round 16
// speedup vs baseline: 1.3470x; 1.0423x over previous
#include <cuda_runtime.h>
#include <cuda_fp16.h>
#include <cstdint>
#include <cstddef>

#define BATCH 8
#define SEQ   2048
#define HID   256
#define INDIM 96

// ---------------- scratch ----------------
__device__ __align__(256) __half g_q[BATCH * SEQ * HID];
__device__ __align__(256) __half g_k[BATCH * SEQ * HID];
__device__ __align__(256) __half g_v[BATCH * SEQ * HID];

// ---------------- helpers ----------------
__device__ __forceinline__ unsigned f2tf32(float x) {
    unsigned r;
    asm("cvt.rna.tf32.f32 %0, %1;" : "=r"(r) : "f"(x));
    return r;
}
__device__ __forceinline__ float tf32f(float x) { return __uint_as_float(f2tf32(x)); }
__device__ __forceinline__ void mma_tf32(float c[4], const unsigned a[4], const unsigned b[2]) {
    asm("mma.sync.aligned.m16n8k8.row.col.f32.tf32.tf32.f32 "
        "{%0,%1,%2,%3}, {%4,%5,%6,%7}, {%8,%9}, {%0,%1,%2,%3};\n"
        : "+f"(c[0]), "+f"(c[1]), "+f"(c[2]), "+f"(c[3])
        : "r"(a[0]), "r"(a[1]), "r"(a[2]), "r"(a[3]), "r"(b[0]), "r"(b[1]));
}
__device__ __forceinline__ void mma_f16(float c[4], const unsigned a[4], unsigned b0, unsigned b1) {
    asm("mma.sync.aligned.m16n8k16.row.col.f32.f16.f16.f32 "
        "{%0,%1,%2,%3}, {%4,%5,%6,%7}, {%8,%9}, {%0,%1,%2,%3};\n"
        : "+f"(c[0]), "+f"(c[1]), "+f"(c[2]), "+f"(c[3])
        : "r"(a[0]), "r"(a[1]), "r"(a[2]), "r"(a[3]), "r"(b0), "r"(b1));
}
__device__ __forceinline__ void cpa16(void* dst_smem, const void* src) {
    unsigned d = (unsigned)__cvta_generic_to_shared(dst_smem);
    asm volatile("cp.async.cg.shared.global [%0], [%1], 16;" :: "r"(d), "l"(src));
}
#define CP_COMMIT() asm volatile("cp.async.commit_group;")
#define CP_WAIT(n)  asm volatile("cp.async.wait_group %0;" :: "n"(n))

__device__ __forceinline__ void ldsm_x4(unsigned r[4], const void* p) {
    unsigned a = (unsigned)__cvta_generic_to_shared(p);
    asm volatile("ldmatrix.sync.aligned.m8n8.x4.shared.b16 {%0,%1,%2,%3}, [%4];"
                 : "=r"(r[0]), "=r"(r[1]), "=r"(r[2]), "=r"(r[3]) : "r"(a));
}
__device__ __forceinline__ void ldsm_x4_t(unsigned r[4], const void* p) {
    unsigned a = (unsigned)__cvta_generic_to_shared(p);
    asm volatile("ldmatrix.sync.aligned.m8n8.x4.trans.shared.b16 {%0,%1,%2,%3}, [%4];"
                 : "=r"(r[0]), "=r"(r[1]), "=r"(r[2]), "=r"(r[3]) : "r"(a));
}
// register-side tf32 hi/lo split from raw fp32 (bit-identical to stored split)
__device__ __forceinline__ void rsplit(float x, unsigned& hi, unsigned& lo) {
    float h = tf32f(x);
    hi = __float_as_uint(h);
    lo = __float_as_uint(x - h);
}

// ================= kernel 1: projections, raw-fp32 smem + cp.async double-buffer =================
// grid (128, 2, 3), 256 threads (8 warps 4m x 2n). K=96 in 6 chunks of 16.
#define XS_ST 20
#define WS_ST 132
#define XB_SZ (128 * XS_ST)
#define WB_SZ (16 * WS_ST)
__global__ void __maxnreg__(120) proj_kernel(
    const float* __restrict__ xq, const float* __restrict__ xk, const float* __restrict__ xv,
    const float* __restrict__ Wq, const float* __restrict__ bq,
    const float* __restrict__ Wk, const float* __restrict__ bk,
    const float* __restrict__ Wv, const float* __restrict__ bv)
{
    const int proj = blockIdx.z;
    const float* x; const float* W; const float* bias; __half* o;
    if (proj == 0)      { x = xq; W = Wq; bias = bq; o = g_q; }
    else if (proj == 1) { x = xk; W = Wk; bias = bk; o = g_k; }
    else                { x = xv; W = Wv; bias = bv; o = g_v; }

    const int row0 = blockIdx.x * 128;
    const int h0   = blockIdx.y * 128;

    __shared__ float xb[2][XB_SZ];
    __shared__ float wb[2][WB_SZ];

    const int tid = threadIdx.x;
    const int warp = tid >> 5, lane = tid & 31;
    const int wm = warp & 3, wn = warp >> 2;
    const int tg = lane & 3, gi = lane >> 2;

    float acc[2][8][4];
#pragma unroll
    for (int mi = 0; mi < 2; mi++)
#pragma unroll
        for (int ni = 0; ni < 8; ni++)
#pragma unroll
            for (int c = 0; c < 4; c++) acc[mi][ni][c] = 0.f;

    // prefetch chunk 0
#pragma unroll
    for (int i = 0; i < 2; i++) {
        int idx = tid + i * 256;
        int r = idx >> 2, c4 = (idx & 3) * 4;
        cpa16(&xb[0][r * XS_ST + c4], x + (size_t)(row0 + r) * INDIM + c4);
    }
#pragma unroll
    for (int i = 0; i < 2; i++) {
        int idx = tid + i * 256;
        int k = idx >> 5, n4 = (idx & 31) * 4;
        cpa16(&wb[0][k * WS_ST + n4], W + (size_t)k * HID + h0 + n4);
    }
    CP_COMMIT();

    const int NC = INDIM / 16;   // 6
    for (int c = 0; c < NC; c++) {
        int cur = c & 1;
        if (c + 1 < NC) {
            int nxt = cur ^ 1, kc = (c + 1) * 16;
#pragma unroll
            for (int i = 0; i < 2; i++) {
                int idx = tid + i * 256;
                int r = idx >> 2, c4 = (idx & 3) * 4;
                cpa16(&xb[nxt][r * XS_ST + c4], x + (size_t)(row0 + r) * INDIM + kc + c4);
            }
#pragma unroll
            for (int i = 0; i < 2; i++) {
                int idx = tid + i * 256;
                int k = idx >> 5, n4 = (idx & 31) * 4;
                cpa16(&wb[nxt][k * WS_ST + n4], W + (size_t)(kc + k) * HID + h0 + n4);
            }
            CP_COMMIT();
            CP_WAIT(1);
        } else {
            CP_WAIT(0);
        }
        __syncthreads();
        const float* xs = xb[cur];
        const float* ws = wb[cur];
#pragma unroll
        for (int ks = 0; ks < 16; ks += 8) {
            unsigned ah[2][4], al[2][4], bh[8][2], bl[8][2];
#pragma unroll
            for (int mi = 0; mi < 2; mi++) {
                int r = wm * 32 + mi * 16 + gi;
                rsplit(xs[r * XS_ST + ks + tg],           ah[mi][0], al[mi][0]);
                rsplit(xs[(r + 8) * XS_ST + ks + tg],     ah[mi][1], al[mi][1]);
                rsplit(xs[r * XS_ST + ks + tg + 4],       ah[mi][2], al[mi][2]);
                rsplit(xs[(r + 8) * XS_ST + ks + tg + 4], ah[mi][3], al[mi][3]);
            }
#pragma unroll
            for (int ni = 0; ni < 8; ni++) {
                int n = wn * 64 + ni * 8 + gi;
                rsplit(ws[(ks + tg) * WS_ST + n],     bh[ni][0], bl[ni][0]);
                rsplit(ws[(ks + tg + 4) * WS_ST + n], bh[ni][1], bl[ni][1]);
            }
#pragma unroll
            for (int mi = 0; mi < 2; mi++)
#pragma unroll
                for (int ni = 0; ni < 8; ni++) {
                    mma_tf32(acc[mi][ni], ah[mi], bh[ni]);
                    mma_tf32(acc[mi][ni], ah[mi], bl[ni]);
                    mma_tf32(acc[mi][ni], al[mi], bh[ni]);
                }
        }
        __syncthreads();
    }
    // epilogue: +bias, fp16 store
#pragma unroll
    for (int mi = 0; mi < 2; mi++) {
        int r0 = row0 + wm * 32 + mi * 16 + gi;
        int r1 = r0 + 8;
#pragma unroll
        for (int ni = 0; ni < 8; ni++) {
            int c = h0 + wn * 64 + ni * 8 + tg * 2;
            float2 bb = *(const float2*)(bias + c);
            *(__half2*)(o + (size_t)r0 * HID + c) =
                __float22half2_rn(make_float2(acc[mi][ni][0] + bb.x, acc[mi][ni][1] + bb.y));
            *(__half2*)(o + (size_t)r1 * HID + c) =
                __float22half2_rn(make_float2(acc[mi][ni][2] + bb.x, acc[mi][ni][3] + bb.y));
        }
    }
}

// ================= kernel 2: fused flash attention + LayerNorm (R10 verified, frozen) =================
#define QT 64
#define KT 64
#define QKV_ST 264
#define PS_ST 72
#define Q_HALVES  (QT * QKV_ST)
#define KV_HALVES (KT * QKV_ST)
#define PS_HALVES (QT * PS_ST)
#define FUSED_SMEM_BYTES ((Q_HALVES + 2 * KV_HALVES + PS_HALVES) * 2 + (256 + 512) * 4)

__global__ void __maxnreg__(120) attn_kernel(
    const int* __restrict__ mask,
    const float* __restrict__ gamma,
    const float* __restrict__ beta,
    float* __restrict__ out)
{
    const int qt = blockIdx.x, b = blockIdx.y;
    extern __shared__ __half smh[];
    __half* Qs = smh;
    __half* Kb = Qs + Q_HALVES;
    __half* Vb = Kb + KV_HALVES;
    __half* Ps = Vb + KV_HALVES;
    float* rsum_sm = (float*)(Ps + PS_HALVES);
    float* rstat   = rsum_sm + 256;

    const int tid = threadIdx.x;
    const int warp = tid >> 5, lane = tid & 31;
    const int wm = warp & 1, wn = warp >> 1;
    const int tg = lane & 3, gi = lane >> 2;
    const int l15 = lane & 15, lhi = (lane >> 4) << 3;

    const __half* Qg = g_q + ((size_t)b * SEQ + qt * QT) * HID;
    const __half* Kg = g_k + (size_t)b * SEQ * HID;
    const __half* Vg = g_v + (size_t)b * SEQ * HID;
    const int* Mg = mask + ((size_t)b * SEQ + qt * QT) * SEQ;

    float accO[2][8][4];
#pragma unroll
    for (int mi = 0; mi < 2; mi++)
#pragma unroll
        for (int ni = 0; ni < 8; ni++)
#pragma unroll
            for (int c = 0; c < 4; c++) accO[mi][ni][c] = 0.f;
    float rs[2][2] = {{0.f, 0.f}, {0.f, 0.f}};

#pragma unroll
    for (int i = 0; i < 8; i++) {
        int idx = tid + i * 256;
        int r = idx >> 5, g = idx & 31;
        cpa16(Qs + r * QKV_ST + g * 8, Qg + (size_t)r * HID + g * 8);
    }
#pragma unroll
    for (int i = 0; i < 8; i++) {
        int idx = tid + i * 256;
        int r = idx >> 5, g = idx & 31;
        cpa16(Kb + r * QKV_ST + g * 8, Kg + (size_t)r * HID + g * 8);
    }
    CP_COMMIT();
#pragma unroll
    for (int i = 0; i < 8; i++) {
        int idx = tid + i * 256;
        int r = idx >> 5, g = idx & 31;
        cpa16(Vb + r * QKV_ST + g * 8, Vg + (size_t)r * HID + g * 8);
    }
    CP_COMMIT();

    const int NKT2 = SEQ / KT;   // 32
    for (int kt = 0; kt < NKT2; kt++) {
        int2 mreg[8];
#pragma unroll
        for (int mi = 0; mi < 2; mi++)
#pragma unroll
            for (int ni = 0; ni < 2; ni++) {
                int r0 = wm * 32 + mi * 16 + gi;
                int c0 = wn * 16 + ni * 8 + tg * 2;
                mreg[(mi * 2 + ni) * 2 + 0] = *(const int2*)(Mg + (size_t)r0 * SEQ + kt * KT + c0);
                mreg[(mi * 2 + ni) * 2 + 1] = *(const int2*)(Mg + (size_t)(r0 + 8) * SEQ + kt * KT + c0);
            }

        CP_WAIT(1);
        __syncthreads();

        float accS[2][2][4];
#pragma unroll
        for (int mi = 0; mi < 2; mi++)
#pragma unroll
            for (int ni = 0; ni < 2; ni++)
#pragma unroll
                for (int c = 0; c < 4; c++) accS[mi][ni][c] = 0.f;
#pragma unroll
        for (int ks = 0; ks < HID; ks += 16) {
            unsigned a[2][4], bb[4];
            ldsm_x4(a[0], Qs + (wm * 32 + l15) * QKV_ST + ks + lhi);
            ldsm_x4(a[1], Qs + (wm * 32 + 16 + l15) * QKV_ST + ks + lhi);
            ldsm_x4(bb,   Kb + (wn * 16 + l15) * QKV_ST + ks + lhi);
            mma_f16(accS[0][0], a[0], bb[0], bb[2]);
            mma_f16(accS[0][1], a[0], bb[1], bb[3]);
            mma_f16(accS[1][0], a[1], bb[0], bb[2]);
            mma_f16(accS[1][1], a[1], bb[1], bb[3]);
        }

        const float scale = 0.0625f;
#pragma unroll
        for (int mi = 0; mi < 2; mi++) {
            int r0 = wm * 32 + mi * 16 + gi;
            int r1 = r0 + 8;
#pragma unroll
            for (int ni = 0; ni < 2; ni++) {
                int c0 = wn * 16 + ni * 8 + tg * 2;
                int2 m0 = mreg[(mi * 2 + ni) * 2 + 0];
                int2 m1 = mreg[(mi * 2 + ni) * 2 + 1];
                float p00 = m0.x ? __expf(accS[mi][ni][0] * scale) : 0.f;
                float p01 = m0.y ? __expf(accS[mi][ni][1] * scale) : 0.f;
                float p10 = m1.x ? __expf(accS[mi][ni][2] * scale) : 0.f;
                float p11 = m1.y ? __expf(accS[mi][ni][3] * scale) : 0.f;
                rs[mi][0] += p00 + p01;
                rs[mi][1] += p10 + p11;
                *(__half2*)(Ps + r0 * PS_ST + c0) = __float22half2_rn(make_float2(p00, p01));
                *(__half2*)(Ps + r1 * PS_ST + c0) = __float22half2_rn(make_float2(p10, p11));
            }
        }
        __syncthreads();

        if (kt + 1 < NKT2) {
#pragma unroll
            for (int i = 0; i < 8; i++) {
                int idx = tid + i * 256;
                int r = idx >> 5, g = idx & 31;
                cpa16(Kb + r * QKV_ST + g * 8, Kg + (size_t)((kt + 1) * KT + r) * HID + g * 8);
            }
            CP_COMMIT();
            CP_WAIT(1);
        } else {
            CP_WAIT(0);
        }
        __syncthreads();

#pragma unroll
        for (int ks = 0; ks < KT; ks += 16) {
            unsigned a[2][4], bb[4][4];
#pragma unroll
            for (int mi = 0; mi < 2; mi++)
                ldsm_x4(a[mi], Ps + (wm * 32 + mi * 16 + l15) * PS_ST + ks + lhi);
#pragma unroll
            for (int nj = 0; nj < 4; nj++)
                ldsm_x4_t(bb[nj], Vb + (size_t)(ks + l15) * QKV_ST + wn * 64 + nj * 16 + lhi);
#pragma unroll
            for (int mi = 0; mi < 2; mi++)
#pragma unroll
                for (int nj = 0; nj < 4; nj++) {
                    mma_f16(accO[mi][nj * 2],     a[mi], bb[nj][0], bb[nj][1]);
                    mma_f16(accO[mi][nj * 2 + 1], a[mi], bb[nj][2], bb[nj][3]);
                }
        }
        __syncthreads();

        if (kt + 1 < NKT2) {
#pragma unroll
            for (int i = 0; i < 8; i++) {
                int idx = tid + i * 256;
                int r = idx >> 5, g = idx & 31;
                cpa16(Vb + r * QKV_ST + g * 8, Vg + (size_t)((kt + 1) * KT + r) * HID + g * 8);
            }
            CP_COMMIT();
        }
    }

#pragma unroll
    for (int mi = 0; mi < 2; mi++) {
#pragma unroll
        for (int h = 0; h < 2; h++) {
            float v = rs[mi][h];
            v += __shfl_xor_sync(0xffffffffu, v, 1);
            v += __shfl_xor_sync(0xffffffffu, v, 2);
            rs[mi][h] = v;
        }
        if (tg == 0) {
            int rl = wm * 32 + mi * 16 + gi;
            rsum_sm[wn * 64 + rl]     = rs[mi][0];
            rsum_sm[wn * 64 + rl + 8] = rs[mi][1];
        }
    }
    __syncthreads();

#pragma unroll
    for (int mi = 0; mi < 2; mi++) {
        int rl0 = wm * 32 + mi * 16 + gi;
        int rl1 = rl0 + 8;
        float t0 = rsum_sm[rl0] + rsum_sm[64 + rl0] + rsum_sm[128 + rl0] + rsum_sm[192 + rl0];
        float t1 = rsum_sm[rl1] + rsum_sm[64 + rl1] + rsum_sm[128 + rl1] + rsum_sm[192 + rl1];
        float i0 = 1.f / t0, i1 = 1.f / t1;
        float s0 = 0.f, s1 = 0.f, q0 = 0.f, q1 = 0.f;
#pragma unroll
        for (int ni = 0; ni < 8; ni++) {
            float v00 = accO[mi][ni][0] * i0; accO[mi][ni][0] = v00;
            float v01 = accO[mi][ni][1] * i0; accO[mi][ni][1] = v01;
            float v10 = accO[mi][ni][2] * i1; accO[mi][ni][2] = v10;
            float v11 = accO[mi][ni][3] * i1; accO[mi][ni][3] = v11;
            s0 += v00 + v01; s1 += v10 + v11;
            q0 += v00 * v00 + v01 * v01;
            q1 += v10 * v10 + v11 * v11;
        }
        s0 += __shfl_xor_sync(0xffffffffu, s0, 1); s0 += __shfl_xor_sync(0xffffffffu, s0, 2);
        s1 += __shfl_xor_sync(0xffffffffu, s1, 1); s1 += __shfl_xor_sync(0xffffffffu, s1, 2);
        q0 += __shfl_xor_sync(0xffffffffu, q0, 1); q0 += __shfl_xor_sync(0xffffffffu, q0, 2);
        q1 += __shfl_xor_sync(0xffffffffu, q1, 1); q1 += __shfl_xor_sync(0xffffffffu, q1, 2);
        if (tg == 0) {
            rstat[wn * 128 + rl0 * 2]     = s0;
            rstat[wn * 128 + rl0 * 2 + 1] = q0;
            rstat[wn * 128 + rl1 * 2]     = s1;
            rstat[wn * 128 + rl1 * 2 + 1] = q1;
        }
    }
    __syncthreads();

#pragma unroll
    for (int mi = 0; mi < 2; mi++) {
        int rl0 = wm * 32 + mi * 16 + gi;
        int rl1 = rl0 + 8;
        float sum0 = rstat[rl0*2] + rstat[128 + rl0*2] + rstat[256 + rl0*2] + rstat[384 + rl0*2];
        float sq0  = rstat[rl0*2+1] + rstat[128 + rl0*2+1] + rstat[256 + rl0*2+1] + rstat[384 + rl0*2+1];
        float sum1 = rstat[rl1*2] + rstat[128 + rl1*2] + rstat[256 + rl1*2] + rstat[384 + rl1*2];
        float sq1  = rstat[rl1*2+1] + rstat[128 + rl1*2+1] + rstat[256 + rl1*2+1] + rstat[384 + rl1*2+1];
        float mu0 = sum0 * (1.f / HID);
        float mu1 = sum1 * (1.f / HID);
        float var0 = sq0 * (1.f / HID) - mu0 * mu0;
        float var1 = sq1 * (1.f / HID) - mu1 * mu1;
        float rstd0 = rsqrtf(var0 + 1e-6f);
        float rstd1 = rsqrtf(var1 + 1e-6f);
        size_t orow0 = ((size_t)b * SEQ + qt * QT + rl0) * HID;
        size_t orow1 = ((size_t)b * SEQ + qt * QT + rl1) * HID;
#pragma unroll
        for (int ni = 0; ni < 8; ni++) {
            int c0 = wn * 64 + ni * 8 + tg * 2;
            float2 gm = *(const float2*)(gamma + c0);
            float2 bt = *(const float2*)(beta + c0);
            float2 o0, o1;
            o0.x = (accO[mi][ni][0] - mu0) * rstd0 * gm.x + bt.x;
            o0.y = (accO[mi][ni][1] - mu0) * rstd0 * gm.y + bt.y;
            o1.x = (accO[mi][ni][2] - mu1) * rstd1 * gm.x + bt.x;
            o1.y = (accO[mi][ni][3] - mu1) * rstd1 * gm.y + bt.y;
            *(float2*)(out + orow0 + c0) = o0;
            *(float2*)(out + orow1 + c0) = o1;
        }
    }
}

// ---------------- launch ----------------
extern "C" void kernel_launch(void* const* d_in, const int* in_sizes, int n_in,
                              void* d_out, int out_size)
{
    const float* q     = (const float*)d_in[0];
    const float* k     = (const float*)d_in[1];
    const float* v     = (const float*)d_in[2];
    const int*   mask  = (const int*)  d_in[3];
    const float* Wq    = (const float*)d_in[4];
    const float* bq    = (const float*)d_in[5];
    const float* Wk    = (const float*)d_in[6];
    const float* bk    = (const float*)d_in[7];
    const float* Wv    = (const float*)d_in[8];
    const float* bv    = (const float*)d_in[9];
    const float* gamma = (const float*)d_in[10];
    const float* beta  = (const float*)d_in[11];
    float* out = (float*)d_out;

    static int inited = 0;
    if (!inited) {
        cudaFuncSetAttribute(attn_kernel, cudaFuncAttributeMaxDynamicSharedMemorySize, FUSED_SMEM_BYTES);
        inited = 1;
    }

    dim3 gp(BATCH * SEQ / 128, HID / 128, 3);
    proj_kernel<<<gp, 256>>>(q, k, v, Wq, bq, Wk, bk, Wv, bv);

    dim3 ga(SEQ / QT, BATCH);
    attn_kernel<<<ga, 256, FUSED_SMEM_BYTES>>>(mask, gamma, beta, out);
}

// round 17
// speedup vs baseline: 1.3733x; 1.0195x over previous
#include <cuda_runtime.h>
#include <cuda_fp16.h>
#include <cstdint>
#include <cstddef>

#define BATCH 8
#define SEQ   2048
#define HID   256
#define INDIM 96

// ---------------- scratch ----------------
__device__ __align__(256) __half g_q[BATCH * SEQ * HID];
__device__ __align__(256) __half g_k[BATCH * SEQ * HID];
__device__ __align__(256) __half g_v[BATCH * SEQ * HID];

// ---------------- helpers ----------------
__device__ __forceinline__ unsigned f2tf32(float x) {
    unsigned r;
    asm("cvt.rna.tf32.f32 %0, %1;" : "=r"(r) : "f"(x));
    return r;
}
__device__ __forceinline__ float tf32f(float x) { return __uint_as_float(f2tf32(x)); }
__device__ __forceinline__ void mma_tf32(float c[4], const unsigned a[4], const unsigned b[2]) {
    asm("mma.sync.aligned.m16n8k8.row.col.f32.tf32.tf32.f32 "
        "{%0,%1,%2,%3}, {%4,%5,%6,%7}, {%8,%9}, {%0,%1,%2,%3};\n"
        : "+f"(c[0]), "+f"(c[1]), "+f"(c[2]), "+f"(c[3])
        : "r"(a[0]), "r"(a[1]), "r"(a[2]), "r"(a[3]), "r"(b[0]), "r"(b[1]));
}
__device__ __forceinline__ void mma_f16(float c[4], const unsigned a[4], unsigned b0, unsigned b1) {
    asm("mma.sync.aligned.m16n8k16.row.col.f32.f16.f16.f32 "
        "{%0,%1,%2,%3}, {%4,%5,%6,%7}, {%8,%9}, {%0,%1,%2,%3};\n"
        : "+f"(c[0]), "+f"(c[1]), "+f"(c[2]), "+f"(c[3])
        : "r"(a[0]), "r"(a[1]), "r"(a[2]), "r"(a[3]), "r"(b0), "r"(b1));
}
__device__ __forceinline__ void cpa16(void* dst_smem, const void* src) {
    unsigned d = (unsigned)__cvta_generic_to_shared(dst_smem);
    asm volatile("cp.async.cg.shared.global [%0], [%1], 16;" :: "r"(d), "l"(src));
}
#define CP_COMMIT() asm volatile("cp.async.commit_group;")
#define CP_WAIT(n)  asm volatile("cp.async.wait_group %0;" :: "n"(n))

__device__ __forceinline__ void ldsm_x4(unsigned r[4], const void* p) {
    unsigned a = (unsigned)__cvta_generic_to_shared(p);
    asm volatile("ldmatrix.sync.aligned.m8n8.x4.shared.b16 {%0,%1,%2,%3}, [%4];"
                 : "=r"(r[0]), "=r"(r[1]), "=r"(r[2]), "=r"(r[3]) : "r"(a));
}
__device__ __forceinline__ void ldsm_x4_t(unsigned r[4], const void* p) {
    unsigned a = (unsigned)__cvta_generic_to_shared(p);
    asm volatile("ldmatrix.sync.aligned.m8n8.x4.trans.shared.b16 {%0,%1,%2,%3}, [%4];"
                 : "=r"(r[0]), "=r"(r[1]), "=r"(r[2]), "=r"(r[3]) : "r"(a));
}
// register-side tf32 hi/lo split from raw fp32
__device__ __forceinline__ void rsplit(float x, unsigned& hi, unsigned& lo) {
    float h = tf32f(x);
    hi = __float_as_uint(h);
    lo = __float_as_uint(x - h);
}

// ================= kernel 1: projections, single-stage smem (K=96 all at once) =================
// grid (128, 2, 3), 256 threads (8 warps 4m x 2n). One fill, one barrier, 12-step MMA loop.
#define XS_ST 100
#define WS_ST 132
#define PROJ_SMEM_BYTES ((128 * XS_ST + INDIM * WS_ST) * 4)
__global__ void __maxnreg__(120) proj_kernel(
    const float* __restrict__ xq, const float* __restrict__ xk, const float* __restrict__ xv,
    const float* __restrict__ Wq, const float* __restrict__ bq,
    const float* __restrict__ Wk, const float* __restrict__ bk,
    const float* __restrict__ Wv, const float* __restrict__ bv)
{
    const int proj = blockIdx.z;
    const float* x; const float* W; const float* bias; __half* o;
    if (proj == 0)      { x = xq; W = Wq; bias = bq; o = g_q; }
    else if (proj == 1) { x = xk; W = Wk; bias = bk; o = g_k; }
    else                { x = xv; W = Wv; bias = bv; o = g_v; }

    const int row0 = blockIdx.x * 128;
    const int h0   = blockIdx.y * 128;

    extern __shared__ float smf[];
    float* xs = smf;                      // 128 x 100 [r][k]
    float* ws = smf + 128 * XS_ST;        // 96 x 132  [k][n]

    const int tid = threadIdx.x;
    const int warp = tid >> 5, lane = tid & 31;
    const int wm = warp & 3, wn = warp >> 2;
    const int tg = lane & 3, gi = lane >> 2;

    // one-shot fill: x 128 rows x 24 float4; W 96 rows x 32 float4
#pragma unroll
    for (int i = 0; i < 12; i++) {
        int idx = tid + i * 256;              // 0..3071
        int r = idx / 24, c4 = (idx % 24) * 4;
        cpa16(xs + r * XS_ST + c4, x + (size_t)(row0 + r) * INDIM + c4);
    }
#pragma unroll
    for (int i = 0; i < 12; i++) {
        int idx = tid + i * 256;              // 0..3071
        int k = idx >> 5, n4 = (idx & 31) * 4;
        cpa16(ws + k * WS_ST + n4, W + (size_t)k * HID + h0 + n4);
    }
    CP_COMMIT();

    float acc[2][8][4];
#pragma unroll
    for (int mi = 0; mi < 2; mi++)
#pragma unroll
        for (int ni = 0; ni < 8; ni++)
#pragma unroll
            for (int c = 0; c < 4; c++) acc[mi][ni][c] = 0.f;

    CP_WAIT(0);
    __syncthreads();

#pragma unroll
    for (int ks = 0; ks < INDIM; ks += 8) {
        unsigned ah[2][4], al[2][4], bh[8][2], bl[8][2];
#pragma unroll
        for (int mi = 0; mi < 2; mi++) {
            int r = wm * 32 + mi * 16 + gi;
            rsplit(xs[r * XS_ST + ks + tg],           ah[mi][0], al[mi][0]);
            rsplit(xs[(r + 8) * XS_ST + ks + tg],     ah[mi][1], al[mi][1]);
            rsplit(xs[r * XS_ST + ks + tg + 4],       ah[mi][2], al[mi][2]);
            rsplit(xs[(r + 8) * XS_ST + ks + tg + 4], ah[mi][3], al[mi][3]);
        }
#pragma unroll
        for (int ni = 0; ni < 8; ni++) {
            int n = wn * 64 + ni * 8 + gi;
            rsplit(ws[(ks + tg) * WS_ST + n],     bh[ni][0], bl[ni][0]);
            rsplit(ws[(ks + tg + 4) * WS_ST + n], bh[ni][1], bl[ni][1]);
        }
#pragma unroll
        for (int mi = 0; mi < 2; mi++)
#pragma unroll
            for (int ni = 0; ni < 8; ni++) {
                mma_tf32(acc[mi][ni], ah[mi], bh[ni]);
                mma_tf32(acc[mi][ni], ah[mi], bl[ni]);
                mma_tf32(acc[mi][ni], al[mi], bh[ni]);
            }
    }

    // epilogue: +bias, fp16 store
#pragma unroll
    for (int mi = 0; mi < 2; mi++) {
        int r0 = row0 + wm * 32 + mi * 16 + gi;
        int r1 = r0 + 8;
#pragma unroll
        for (int ni = 0; ni < 8; ni++) {
            int c = h0 + wn * 64 + ni * 8 + tg * 2;
            float2 bb = *(const float2*)(bias + c);
            *(__half2*)(o + (size_t)r0 * HID + c) =
                __float22half2_rn(make_float2(acc[mi][ni][0] + bb.x, acc[mi][ni][1] + bb.y));
            *(__half2*)(o + (size_t)r1 * HID + c) =
                __float22half2_rn(make_float2(acc[mi][ni][2] + bb.x, acc[mi][ni][3] + bb.y));
        }
    }
}

// ================= kernel 2: fused flash attention + LayerNorm (R10/R16 verified, frozen) =================
#define QT 64
#define KT 64
#define QKV_ST 264
#define PS_ST 72
#define Q_HALVES  (QT * QKV_ST)
#define KV_HALVES (KT * QKV_ST)
#define PS_HALVES (QT * PS_ST)
#define FUSED_SMEM_BYTES ((Q_HALVES + 2 * KV_HALVES + PS_HALVES) * 2 + (256 + 512) * 4)

__global__ void __maxnreg__(120) attn_kernel(
    const int* __restrict__ mask,
    const float* __restrict__ gamma,
    const float* __restrict__ beta,
    float* __restrict__ out)
{
    const int qt = blockIdx.x, b = blockIdx.y;
    extern __shared__ __half smh[];
    __half* Qs = smh;
    __half* Kb = Qs + Q_HALVES;
    __half* Vb = Kb + KV_HALVES;
    __half* Ps = Vb + KV_HALVES;
    float* rsum_sm = (float*)(Ps + PS_HALVES);
    float* rstat   = rsum_sm + 256;

    const int tid = threadIdx.x;
    const int warp = tid >> 5, lane = tid & 31;
    const int wm = warp & 1, wn = warp >> 1;
    const int tg = lane & 3, gi = lane >> 2;
    const int l15 = lane & 15, lhi = (lane >> 4) << 3;

    const __half* Qg = g_q + ((size_t)b * SEQ + qt * QT) * HID;
    const __half* Kg = g_k + (size_t)b * SEQ * HID;
    const __half* Vg = g_v + (size_t)b * SEQ * HID;
    const int* Mg = mask + ((size_t)b * SEQ + qt * QT) * SEQ;

    float accO[2][8][4];
#pragma unroll
    for (int mi = 0; mi < 2; mi++)
#pragma unroll
        for (int ni = 0; ni < 8; ni++)
#pragma unroll
            for (int c = 0; c < 4; c++) accO[mi][ni][c] = 0.f;
    float rs[2][2] = {{0.f, 0.f}, {0.f, 0.f}};

#pragma unroll
    for (int i = 0; i < 8; i++) {
        int idx = tid + i * 256;
        int r = idx >> 5, g = idx & 31;
        cpa16(Qs + r * QKV_ST + g * 8, Qg + (size_t)r * HID + g * 8);
    }
#pragma unroll
    for (int i = 0; i < 8; i++) {
        int idx = tid + i * 256;
        int r = idx >> 5, g = idx & 31;
        cpa16(Kb + r * QKV_ST + g * 8, Kg + (size_t)r * HID + g * 8);
    }
    CP_COMMIT();
#pragma unroll
    for (int i = 0; i < 8; i++) {
        int idx = tid + i * 256;
        int r = idx >> 5, g = idx & 31;
        cpa16(Vb + r * QKV_ST + g * 8, Vg + (size_t)r * HID + g * 8);
    }
    CP_COMMIT();

    const int NKT2 = SEQ / KT;   // 32
    for (int kt = 0; kt < NKT2; kt++) {
        int2 mreg[8];
#pragma unroll
        for (int mi = 0; mi < 2; mi++)
#pragma unroll
            for (int ni = 0; ni < 2; ni++) {
                int r0 = wm * 32 + mi * 16 + gi;
                int c0 = wn * 16 + ni * 8 + tg * 2;
                mreg[(mi * 2 + ni) * 2 + 0] = *(const int2*)(Mg + (size_t)r0 * SEQ + kt * KT + c0);
                mreg[(mi * 2 + ni) * 2 + 1] = *(const int2*)(Mg + (size_t)(r0 + 8) * SEQ + kt * KT + c0);
            }

        CP_WAIT(1);
        __syncthreads();

        float accS[2][2][4];
#pragma unroll
        for (int mi = 0; mi < 2; mi++)
#pragma unroll
            for (int ni = 0; ni < 2; ni++)
#pragma unroll
                for (int c = 0; c < 4; c++) accS[mi][ni][c] = 0.f;
#pragma unroll
        for (int ks = 0; ks < HID; ks += 16) {
            unsigned a[2][4], bb[4];
            ldsm_x4(a[0], Qs + (wm * 32 + l15) * QKV_ST + ks + lhi);
            ldsm_x4(a[1], Qs + (wm * 32 + 16 + l15) * QKV_ST + ks + lhi);
            ldsm_x4(bb,   Kb + (wn * 16 + l15) * QKV_ST + ks + lhi);
            mma_f16(accS[0][0], a[0], bb[0], bb[2]);
            mma_f16(accS[0][1], a[0], bb[1], bb[3]);
            mma_f16(accS[1][0], a[1], bb[0], bb[2]);
            mma_f16(accS[1][1], a[1], bb[1], bb[3]);
        }

        const float scale = 0.0625f;
#pragma unroll
        for (int mi = 0; mi < 2; mi++) {
            int r0 = wm * 32 + mi * 16 + gi;
            int r1 = r0 + 8;
#pragma unroll
            for (int ni = 0; ni < 2; ni++) {
                int c0 = wn * 16 + ni * 8 + tg * 2;
                int2 m0 = mreg[(mi * 2 + ni) * 2 + 0];
                int2 m1 = mreg[(mi * 2 + ni) * 2 + 1];
                float p00 = m0.x ? __expf(accS[mi][ni][0] * scale) : 0.f;
                float p01 = m0.y ? __expf(accS[mi][ni][1] * scale) : 0.f;
                float p10 = m1.x ? __expf(accS[mi][ni][2] * scale) : 0.f;
                float p11 = m1.y ? __expf(accS[mi][ni][3] * scale) : 0.f;
                rs[mi][0] += p00 + p01;
                rs[mi][1] += p10 + p11;
                *(__half2*)(Ps + r0 * PS_ST + c0) = __float22half2_rn(make_float2(p00, p01));
                *(__half2*)(Ps + r1 * PS_ST + c0) = __float22half2_rn(make_float2(p10, p11));
            }
        }
        __syncthreads();

        if (kt + 1 < NKT2) {
#pragma unroll
            for (int i = 0; i < 8; i++) {
                int idx = tid + i * 256;
                int r = idx >> 5, g = idx & 31;
                cpa16(Kb + r * QKV_ST + g * 8, Kg + (size_t)((kt + 1) * KT + r) * HID + g * 8);
            }
            CP_COMMIT();
            CP_WAIT(1);
        } else {
            CP_WAIT(0);
        }
        __syncthreads();

#pragma unroll
        for (int ks = 0; ks < KT; ks += 16) {
            unsigned a[2][4], bb[4][4];
#pragma unroll
            for (int mi = 0; mi < 2; mi++)
                ldsm_x4(a[mi], Ps + (wm * 32 + mi * 16 + l15) * PS_ST + ks + lhi);
#pragma unroll
            for (int nj = 0; nj < 4; nj++)
                ldsm_x4_t(bb[nj], Vb + (size_t)(ks + l15) * QKV_ST + wn * 64 + nj * 16 + lhi);
#pragma unroll
            for (int mi = 0; mi < 2; mi++)
#pragma unroll
                for (int nj = 0; nj < 4; nj++) {
                    mma_f16(accO[mi][nj * 2],     a[mi], bb[nj][0], bb[nj][1]);
                    mma_f16(accO[mi][nj * 2 + 1], a[mi], bb[nj][2], bb[nj][3]);
                }
        }
        __syncthreads();

        if (kt + 1 < NKT2) {
#pragma unroll
            for (int i = 0; i < 8; i++) {
                int idx = tid + i * 256;
                int r = idx >> 5, g = idx & 31;
                cpa16(Vb + r * QKV_ST + g * 8, Vg + (size_t)((kt + 1) * KT + r) * HID + g * 8);
            }
            CP_COMMIT();
        }
    }

#pragma unroll
    for (int mi = 0; mi < 2; mi++) {
#pragma unroll
        for (int h = 0; h < 2; h++) {
            float v = rs[mi][h];
            v += __shfl_xor_sync(0xffffffffu, v, 1);
            v += __shfl_xor_sync(0xffffffffu, v, 2);
            rs[mi][h] = v;
        }
        if (tg == 0) {
            int rl = wm * 32 + mi * 16 + gi;
            rsum_sm[wn * 64 + rl]     = rs[mi][0];
            rsum_sm[wn * 64 + rl + 8] = rs[mi][1];
        }
    }
    __syncthreads();

#pragma unroll
    for (int mi = 0; mi < 2; mi++) {
        int rl0 = wm * 32 + mi * 16 + gi;
        int rl1 = rl0 + 8;
        float t0 = rsum_sm[rl0] + rsum_sm[64 + rl0] + rsum_sm[128 + rl0] + rsum_sm[192 + rl0];
        float t1 = rsum_sm[rl1] + rsum_sm[64 + rl1] + rsum_sm[128 + rl1] + rsum_sm[192 + rl1];
        float i0 = 1.f / t0, i1 = 1.f / t1;
        float s0 = 0.f, s1 = 0.f, q0 = 0.f, q1 = 0.f;
#pragma unroll
        for (int ni = 0; ni < 8; ni++) {
            float v00 = accO[mi][ni][0] * i0; accO[mi][ni][0] = v00;
            float v01 = accO[mi][ni][1] * i0; accO[mi][ni][1] = v01;
            float v10 = accO[mi][ni][2] * i1; accO[mi][ni][2] = v10;
            float v11 = accO[mi][ni][3] * i1; accO[mi][ni][3] = v11;
            s0 += v00 + v01; s1 += v10 + v11;
            q0 += v00 * v00 + v01 * v01;
            q1 += v10 * v10 + v11 * v11;
        }
        s0 += __shfl_xor_sync(0xffffffffu, s0, 1); s0 += __shfl_xor_sync(0xffffffffu, s0, 2);
        s1 += __shfl_xor_sync(0xffffffffu, s1, 1); s1 += __shfl_xor_sync(0xffffffffu, s1, 2);
        q0 += __shfl_xor_sync(0xffffffffu, q0, 1); q0 += __shfl_xor_sync(0xffffffffu, q0, 2);
        q1 += __shfl_xor_sync(0xffffffffu, q1, 1); q1 += __shfl_xor_sync(0xffffffffu, q1, 2);
        if (tg == 0) {
            rstat[wn * 128 + rl0 * 2]     = s0;
            rstat[wn * 128 + rl0 * 2 + 1] = q0;
            rstat[wn * 128 + rl1 * 2]     = s1;
            rstat[wn * 128 + rl1 * 2 + 1] = q1;
        }
    }
    __syncthreads();

#pragma unroll
    for (int mi = 0; mi < 2; mi++) {
        int rl0 = wm * 32 + mi * 16 + gi;
        int rl1 = rl0 + 8;
        float sum0 = rstat[rl0*2] + rstat[128 + rl0*2] + rstat[256 + rl0*2] + rstat[384 + rl0*2];
        float sq0  = rstat[rl0*2+1] + rstat[128 + rl0*2+1] + rstat[256 + rl0*2+1] + rstat[384 + rl0*2+1];
        float sum1 = rstat[rl1*2] + rstat[128 + rl1*2] + rstat[256 + rl1*2] + rstat[384 + rl1*2];
        float sq1  = rstat[rl1*2+1] + rstat[128 + rl1*2+1] + rstat[256 + rl1*2+1] + rstat[384 + rl1*2+1];
        float mu0 = sum0 * (1.f / HID);
        float mu1 = sum1 * (1.f / HID);
        float var0 = sq0 * (1.f / HID) - mu0 * mu0;
        float var1 = sq1 * (1.f / HID) - mu1 * mu1;
        float rstd0 = rsqrtf(var0 + 1e-6f);
        float rstd1 = rsqrtf(var1 + 1e-6f);
        size_t orow0 = ((size_t)b * SEQ + qt * QT + rl0) * HID;
        size_t orow1 = ((size_t)b * SEQ + qt * QT + rl1) * HID;
#pragma unroll
        for (int ni = 0; ni < 8; ni++) {
            int c0 = wn * 64 + ni * 8 + tg * 2;
            float2 gm = *(const float2*)(gamma + c0);
            float2 bt = *(const float2*)(beta + c0);
            float2 o0, o1;
            o0.x = (accO[mi][ni][0] - mu0) * rstd0 * gm.x + bt.x;
            o0.y = (accO[mi][ni][1] - mu0) * rstd0 * gm.y + bt.y;
            o1.x = (accO[mi][ni][2] - mu1) * rstd1 * gm.x + bt.x;
            o1.y = (accO[mi][ni][3] - mu1) * rstd1 * gm.y + bt.y;
            *(float2*)(out + orow0 + c0) = o0;
            *(float2*)(out + orow1 + c0) = o1;
        }
    }
}

// ---------------- launch ----------------
extern "C" void kernel_launch(void* const* d_in, const int* in_sizes, int n_in,
                              void* d_out, int out_size)
{
    const float* q     = (const float*)d_in[0];
    const float* k     = (const float*)d_in[1];
    const float* v     = (const float*)d_in[2];
    const int*   mask  = (const int*)  d_in[3];
    const float* Wq    = (const float*)d_in[4];
    const float* bq    = (const float*)d_in[5];
    const float* Wk    = (const float*)d_in[6];
    const float* bk    = (const float*)d_in[7];
    const float* Wv    = (const float*)d_in[8];
    const float* bv    = (const float*)d_in[9];
    const float* gamma = (const float*)d_in[10];
    const float* beta  = (const float*)d_in[11];
    float* out = (float*)d_out;

    static int inited = 0;
    if (!inited) {
        cudaFuncSetAttribute(proj_kernel, cudaFuncAttributeMaxDynamicSharedMemorySize, PROJ_SMEM_BYTES);
        cudaFuncSetAttribute(attn_kernel, cudaFuncAttributeMaxDynamicSharedMemorySize, FUSED_SMEM_BYTES);
        inited = 1;
    }

    dim3 gp(BATCH * SEQ / 128, HID / 128, 3);
    proj_kernel<<<gp, 256, PROJ_SMEM_BYTES>>>(q, k, v, Wq, bq, Wk, bk, Wv, bv);

    dim3 ga(SEQ / QT, BATCH);
    attn_kernel<<<ga, 256, FUSED_SMEM_BYTES>>>(mask, gamma, beta, out);
}